// round 1
// baseline (speedup 1.0000x reference)
#include <cuda_runtime.h>

// Problem constants (fixed by the dataset)
#define B_   16
#define NNODE 7
#define HID_ 256
#define C_   256
#define P_   (96 * 96)      // 9216 pixels
#define P4_  (P_ / 4)       // 2304 float4 chunks

// One block per (b, c). 256 threads; thread t owns hidden index h = t.
//
// Math (softmax shift-invariance): attn over nodes is independent of the
// pixel, so out[b,c,p] == relu( sum_h y[b,h] * W[h,c] ) for all p, where
// y[b,h] = sum_n softmax_n(x[b,n,:].nfh)[n] * x[b,n,h].
__global__ __launch_bounds__(256)
void g2f_savemem_kernel(const float* __restrict__ x,     // (B, NNODE, HID)
                        const float* __restrict__ nfh,   // (HID)
                        const float* __restrict__ W,     // (HID, C) row-major
                        float* __restrict__ out)         // (B, C, P)
{
    const int c = blockIdx.x;      // 0..255
    const int b = blockIdx.y;      // 0..15
    const int t = threadIdx.x;     // 0..255 == h
    const int lane = t & 31;
    const int warp = t >> 5;

    __shared__ float wsum[8][NNODE];   // per-warp partial s_hid
    __shared__ float s_hid[NNODE];
    __shared__ float wred[8];          // per-warp partial v
    __shared__ float v_sh;

    // ---- load x[b, :, t] and nfh[t] ----
    const float* xb = x + (size_t)b * NNODE * HID_;
    float xh[NNODE];
#pragma unroll
    for (int n = 0; n < NNODE; n++) xh[n] = xb[n * HID_ + t];
    const float nf = nfh[t];

    // ---- s_hid[n] = sum_h x[b,n,h] * nfh[h] : 7 simultaneous block reductions ----
    float p[NNODE];
#pragma unroll
    for (int n = 0; n < NNODE; n++) p[n] = xh[n] * nf;
#pragma unroll
    for (int off = 16; off > 0; off >>= 1) {
#pragma unroll
        for (int n = 0; n < NNODE; n++)
            p[n] += __shfl_down_sync(0xFFFFFFFFu, p[n], off);
    }
    if (lane == 0) {
#pragma unroll
        for (int n = 0; n < NNODE; n++) wsum[warp][n] = p[n];
    }
    __syncthreads();
    if (t < NNODE) {
        float s = 0.f;
#pragma unroll
        for (int w = 0; w < 8; w++) s += wsum[w][t];
        s_hid[t] = s;
    }
    __syncthreads();

    // ---- softmax over 7 nodes (redundant per thread; trivial) ----
    float sv[NNODE];
#pragma unroll
    for (int n = 0; n < NNODE; n++) sv[n] = s_hid[n];
    float m = sv[0];
#pragma unroll
    for (int n = 1; n < NNODE; n++) m = fmaxf(m, sv[n]);
    float esum = 0.f;
    float a[NNODE];
#pragma unroll
    for (int n = 0; n < NNODE; n++) { a[n] = __expf(sv[n] - m); esum += a[n]; }
    const float inv = 1.0f / esum;
#pragma unroll
    for (int n = 0; n < NNODE; n++) a[n] *= inv;

    // ---- v = sum_h ( sum_n a[n]*x[b,n,h] ) * W[h,c] : block reduction ----
    float y = 0.f;
#pragma unroll
    for (int n = 0; n < NNODE; n++) y = fmaf(a[n], xh[n], y);
    float pv = y * W[t * C_ + c];
#pragma unroll
    for (int off = 16; off > 0; off >>= 1)
        pv += __shfl_down_sync(0xFFFFFFFFu, pv, off);
    if (lane == 0) wred[warp] = pv;
    __syncthreads();
    if (t == 0) {
        float s = 0.f;
#pragma unroll
        for (int w = 0; w < 8; w++) s += wred[w];
        v_sh = fmaxf(s, 0.0f);       // relu
    }
    __syncthreads();

    // ---- broadcast-write 9216 floats (2304 float4) ----
    const float v = v_sh;
    const float4 val = make_float4(v, v, v, v);
    float4* o = reinterpret_cast<float4*>(out + (size_t)(b * C_ + c) * P_);
#pragma unroll
    for (int i = 0; i < P4_ / 256; i++)     // 9 iterations
        o[i * 256 + t] = val;
}

extern "C" void kernel_launch(void* const* d_in, const int* in_sizes, int n_in,
                              void* d_out, int out_size)
{
    // metadata order: input, res_feature, node_fea_for_res, node_fea_for_hidden, weight
    const float* x   = (const float*)d_in[0];  // (1,16,7,256)
    // d_in[1] res_feature and d_in[2] node_fea_for_res cancel in the softmax — unused.
    const float* nfh = (const float*)d_in[3];  // (256,1)
    const float* W   = (const float*)d_in[4];  // (256,256)
    float* out = (float*)d_out;                // (16,256,96,96)

    dim3 grid(C_, B_);
    g2f_savemem_kernel<<<grid, 256>>>(x, nfh, W, out);
}